// round 14
// baseline (speedup 1.0000x reference)
#include <cuda_runtime.h>
#include <cuda_bf16.h>
#include <math.h>
#include <stdint.h>

#define B_   2
#define NQ_  2048
#define NKV_ 2048
#define D_   1024
#define H_   16
#define DH_  64

// ---- Scratch (allocation-free) ----
__device__ __nv_bfloat16 g_qhi[B_ * NQ_ * D_];
__device__ __nv_bfloat16 g_qlo[B_ * NQ_ * D_];
__device__ __nv_bfloat16 g_kvhi[B_ * NKV_ * D_];
__device__ __nv_bfloat16 g_kvlo[B_ * NKV_ * D_];
__device__ __nv_bfloat16 g_Wqhi[D_ * D_], g_Wqlo[D_ * D_];
__device__ __nv_bfloat16 g_Wkhi[D_ * D_], g_Wklo[D_ * D_];
__device__ __nv_bfloat16 g_Wvhi[D_ * D_], g_Wvlo[D_ * D_];
__device__ __nv_bfloat16 g_Wohi[D_ * D_], g_Wolo[D_ * D_];
__device__ __nv_bfloat16 g_Qhi[B_ * NQ_ * D_], g_Qlo[B_ * NQ_ * D_];
__device__ __nv_bfloat16 g_Khi[B_ * NKV_ * D_], g_Klo[B_ * NKV_ * D_];
__device__ __nv_bfloat16 g_Vhi[B_ * NKV_ * D_], g_Vlo[B_ * NKV_ * D_];
__device__ __nv_bfloat16 g_Ophi[B_ * NQ_ * D_], g_Oplo[B_ * NQ_ * D_];

__device__ __forceinline__ uint32_t smem_u32(const void* p) {
    uint32_t a;
    asm("{ .reg .u64 t; cvta.to.shared.u64 t, %1; cvt.u32.u64 %0, t; }"
        : "=r"(a) : "l"(p));
    return a;
}

__device__ __forceinline__ void mma_bf16(float* d, const uint32_t* a,
                                         uint32_t b0, uint32_t b1) {
    asm volatile(
        "mma.sync.aligned.m16n8k16.row.col.f32.bf16.bf16.f32 "
        "{%0,%1,%2,%3}, {%4,%5,%6,%7}, {%8,%9}, {%0,%1,%2,%3};"
        : "+f"(d[0]), "+f"(d[1]), "+f"(d[2]), "+f"(d[3])
        : "r"(a[0]), "r"(a[1]), "r"(a[2]), "r"(a[3]), "r"(b0), "r"(b1));
}

__device__ __forceinline__ void ldmx4(uint32_t* r, uint32_t addr) {
    asm volatile(
        "ldmatrix.sync.aligned.m8n8.x4.shared.b16 {%0,%1,%2,%3}, [%4];"
        : "=r"(r[0]), "=r"(r[1]), "=r"(r[2]), "=r"(r[3]) : "r"(addr));
}

__device__ __forceinline__ void ldmx4t(uint32_t* r, uint32_t addr) {
    asm volatile(
        "ldmatrix.sync.aligned.m8n8.x4.trans.shared.b16 {%0,%1,%2,%3}, [%4];"
        : "=r"(r[0]), "=r"(r[1]), "=r"(r[2]), "=r"(r[3]) : "r"(addr));
}

__device__ __forceinline__ uint32_t pack_bf16x2(float lo, float hi) {
    uint32_t r;
    asm("cvt.rn.bf16x2.f32 %0, %1, %2;" : "=r"(r) : "f"(hi), "f"(lo));
    return r;
}

#define CP16(dst, src) \
    asm volatile("cp.async.cg.shared.global [%0], [%1], 16;" :: "r"(dst), "l"(src))
#define CP_COMMIT() asm volatile("cp.async.commit_group;" ::: "memory")
#define CP_WAIT0()  asm volatile("cp.async.wait_group 0;" ::: "memory")

// ===========================================================================
// split: fp32 -> hi/lo bf16
// ===========================================================================
__global__ __launch_bounds__(256) void split_kernel(
    const float* __restrict__ x, __nv_bfloat16* __restrict__ hi,
    __nv_bfloat16* __restrict__ lo)
{
    const int i = (blockIdx.x * 256 + threadIdx.x) * 4;
    const float4 v = *(const float4*)(x + i);
    __nv_bfloat16 h0 = __float2bfloat16(v.x), h1 = __float2bfloat16(v.y);
    __nv_bfloat16 h2 = __float2bfloat16(v.z), h3 = __float2bfloat16(v.w);
    __nv_bfloat16 l0 = __float2bfloat16(v.x - __bfloat162float(h0));
    __nv_bfloat16 l1 = __float2bfloat16(v.y - __bfloat162float(h1));
    __nv_bfloat16 l2 = __float2bfloat16(v.z - __bfloat162float(h2));
    __nv_bfloat16 l3 = __float2bfloat16(v.w - __bfloat162float(h3));
    __nv_bfloat162 hp0, hp1, lp0, lp1;
    hp0.x = h0; hp0.y = h1; hp1.x = h2; hp1.y = h3;
    lp0.x = l0; lp0.y = l1; lp1.x = l2; lp1.y = l3;
    uint2 hv, lv;
    hv.x = *(uint32_t*)&hp0; hv.y = *(uint32_t*)&hp1;
    lv.x = *(uint32_t*)&lp0; lv.y = *(uint32_t*)&lp1;
    *(uint2*)(hi + i) = hv;
    *(uint2*)(lo + i) = lv;
}

// ===========================================================================
// Pre-split HMMA GEMM: C = A[M,K] @ W[N,K]^T + bias (bf16x3).
// CTA 128x128, K-chunk 32, 2 CTAs/SM. MMA issue is TERM-MAJOR across 8
// independent accumulators (dependency distance 8) to hide HMMA RAW latency.
// ===========================================================================
#define GM 4096
#define GN 1024
#define GK 1024
#define GPITCH 80
#define GT  (128 * GPITCH)       // 10240 per tile
#define GST (4 * GT)             // 40960 per stage
#define SM_TOTAL (2 * GST)       // 81920

template <int OUTMODE>
__global__ __launch_bounds__(256, 2) void gemm_ps(
    const __nv_bfloat16* __restrict__ Ahi, const __nv_bfloat16* __restrict__ Alo,
    const __nv_bfloat16* __restrict__ Whi, const __nv_bfloat16* __restrict__ Wlo,
    const float* __restrict__ bias, float* __restrict__ C,
    __nv_bfloat16* __restrict__ Chi, __nv_bfloat16* __restrict__ Clo,
    float scale)
{
    extern __shared__ char smem[];
    const uint32_t sb = smem_u32(smem);
    const int tid  = threadIdx.x;
    const int wid  = tid >> 5;
    const int lane = tid & 31;
    const int bm = blockIdx.y * 128;
    const int bn = blockIdx.x * 128;
    const int warp_m = wid >> 1;         // 0..3
    const int warp_n = wid & 1;          // 0..1

    float acc[2][8][4];
#pragma unroll
    for (int i = 0; i < 2; i++)
#pragma unroll
        for (int j = 0; j < 8; j++)
#pragma unroll
            for (int k = 0; k < 4; k++) acc[i][j][k] = 0.f;

    auto issue_chunk = [&](int chunk) {
        const uint32_t base = sb + (uint32_t)((chunk & 1) * GST);
        const int kc = chunk * 32;
#pragma unroll
        for (int it = 0; it < 8; it++) {
            const int t   = it >> 1;
            const int sub = (it & 1) * 256 + tid;
            const int r   = sub >> 2;
            const int c   = sub & 3;
            const uint32_t dst = base + (uint32_t)(t * GT + r * GPITCH + c * 16);
            const __nv_bfloat16* src;
            if      (t == 0) src = Ahi + (long)(bm + r) * GK + kc + c * 8;
            else if (t == 1) src = Alo + (long)(bm + r) * GK + kc + c * 8;
            else if (t == 2) src = Whi + (long)(bn + r) * GK + kc + c * 8;
            else             src = Wlo + (long)(bn + r) * GK + kc + c * 8;
            CP16(dst, src);
        }
        CP_COMMIT();
    };

    issue_chunk(0);

    for (int chunk = 0; chunk < GK / 32; chunk++) {
        CP_WAIT0();
        __syncthreads();
        if (chunk + 1 < GK / 32) issue_chunk(chunk + 1);

        const uint32_t base = sb + (uint32_t)((chunk & 1) * GST);
#pragma unroll
        for (int ks = 0; ks < 2; ks++) {
            uint32_t ah[2][4], al[2][4];
#pragma unroll
            for (int mt = 0; mt < 2; mt++) {
                const uint32_t ra = (uint32_t)((warp_m * 32 + mt * 16 + (lane & 15)) * GPITCH
                                  + ks * 32 + (lane >> 4) * 16);
                ldmx4(ah[mt], base + ra);
                ldmx4(al[mt], base + GT + ra);
            }
            // process B tiles in pairs -> 8 independent accumulators per term
#pragma unroll
            for (int gp = 0; gp < 2; gp++) {
                uint32_t bh[2][4], bl[2][4];
#pragma unroll
                for (int gg = 0; gg < 2; gg++) {
                    const int g = gp * 2 + gg;
                    const uint32_t rb = (uint32_t)((warp_n * 64 + g * 16 + (lane & 15)) * GPITCH
                                      + ks * 32 + (lane >> 4) * 16);
                    ldmx4(bh[gg], base + 2 * GT + rb);
                    ldmx4(bl[gg], base + 3 * GT + rb);
                }
                // term 1: hi*hi (8 indep accs)
#pragma unroll
                for (int gg = 0; gg < 2; gg++)
#pragma unroll
                    for (int mt = 0; mt < 2; mt++)
#pragma unroll
                        for (int o = 0; o < 2; o++)
                            mma_bf16(acc[mt][(gp * 2 + gg) * 2 + o], ah[mt],
                                     bh[gg][o], bh[gg][o + 2]);
                // term 2: hi*lo
#pragma unroll
                for (int gg = 0; gg < 2; gg++)
#pragma unroll
                    for (int mt = 0; mt < 2; mt++)
#pragma unroll
                        for (int o = 0; o < 2; o++)
                            mma_bf16(acc[mt][(gp * 2 + gg) * 2 + o], ah[mt],
                                     bl[gg][o], bl[gg][o + 2]);
                // term 3: lo*hi
#pragma unroll
                for (int gg = 0; gg < 2; gg++)
#pragma unroll
                    for (int mt = 0; mt < 2; mt++)
#pragma unroll
                        for (int o = 0; o < 2; o++)
                            mma_bf16(acc[mt][(gp * 2 + gg) * 2 + o], al[mt],
                                     bh[gg][o], bh[gg][o + 2]);
            }
        }
    }

    const int rq = lane >> 2;
    const int cq = (lane & 3) * 2;
#pragma unroll
    for (int mt = 0; mt < 2; mt++) {
        const int r0 = bm + warp_m * 32 + mt * 16 + rq;
#pragma unroll
        for (int nt = 0; nt < 8; nt++) {
            const int c = bn + warp_n * 64 + nt * 8 + cq;
            const float2 bv = *(const float2*)&bias[c];
            if (OUTMODE == 0) {
                float2 o0, o1;
                o0.x = acc[mt][nt][0] + bv.x;
                o0.y = acc[mt][nt][1] + bv.y;
                o1.x = acc[mt][nt][2] + bv.x;
                o1.y = acc[mt][nt][3] + bv.y;
                *(float2*)&C[(long)r0 * GN + c] = o0;
                *(float2*)&C[(long)(r0 + 8) * GN + c] = o1;
            } else {
                const float v0 = (acc[mt][nt][0] + bv.x) * scale;
                const float v1 = (acc[mt][nt][1] + bv.y) * scale;
                const float v2 = (acc[mt][nt][2] + bv.x) * scale;
                const float v3 = (acc[mt][nt][3] + bv.y) * scale;
                const float h0 = __bfloat162float(__float2bfloat16(v0));
                const float h1 = __bfloat162float(__float2bfloat16(v1));
                const float h2 = __bfloat162float(__float2bfloat16(v2));
                const float h3 = __bfloat162float(__float2bfloat16(v3));
                *(uint32_t*)&Chi[(long)r0 * GN + c]       = pack_bf16x2(v0, v1);
                *(uint32_t*)&Chi[(long)(r0 + 8) * GN + c] = pack_bf16x2(v2, v3);
                *(uint32_t*)&Clo[(long)r0 * GN + c]       = pack_bf16x2(v0 - h0, v1 - h1);
                *(uint32_t*)&Clo[(long)(r0 + 8) * GN + c] = pack_bf16x2(v2 - h2, v3 - h3);
            }
        }
    }
}

// ===========================================================================
// HMMA flash attention with term-major MMA issue (distance-8 chains).
// 64 q-rows, 4 warps, KV tiles of 64 double-buffered, Q overlaid on stage 1.
// ===========================================================================
#define FPITCH 144
#define FT  (64 * FPITCH)
#define FST (4 * FT)
#define FSM_QHI (FST)
#define FSM_QLO (FST + FT)
#define FSM_TOTAL (2 * FST)        // 73728

__global__ __launch_bounds__(128) void flash_mma(
    const __nv_bfloat16* __restrict__ Qhi, const __nv_bfloat16* __restrict__ Qlo,
    const __nv_bfloat16* __restrict__ Khi, const __nv_bfloat16* __restrict__ Klo,
    const __nv_bfloat16* __restrict__ Vhi, const __nv_bfloat16* __restrict__ Vlo,
    __nv_bfloat16* __restrict__ Ophi, __nv_bfloat16* __restrict__ Oplo)
{
    extern __shared__ char smem[];
    const uint32_t sb = smem_u32(smem);
    const int tid  = threadIdx.x;
    const int wid  = tid >> 5;
    const int lane = tid & 31;
    const int qt = blockIdx.x, h = blockIdx.y, b = blockIdx.z;

    const long qrow0 = (long)b * NQ_ + qt * 64;
    const long krow0 = (long)b * NKV_;
    const int  col0  = h * DH_;

    auto issueKV = [&](int kt) {
        const uint32_t base = sb + (uint32_t)((kt & 1) * FST);
#pragma unroll
        for (int it = 0; it < 4; it++) {
            const int idx = it * 128 + tid;
            const int r = idx >> 3, c = idx & 7;
            const uint32_t doff = (uint32_t)(r * FPITCH + c * 16);
            const long goff = (krow0 + kt * 64 + r) * D_ + col0 + c * 8;
            CP16(base + doff,          Khi + goff);
            CP16(base + FT + doff,     Klo + goff);
            CP16(base + 2 * FT + doff, Vhi + goff);
            CP16(base + 3 * FT + doff, Vlo + goff);
        }
        CP_COMMIT();
    };

#pragma unroll
    for (int it = 0; it < 4; it++) {
        const int idx = it * 128 + tid;
        const int r = idx >> 3, c = idx & 7;
        const uint32_t doff = (uint32_t)(r * FPITCH + c * 16);
        const long goff = (qrow0 + r) * D_ + col0 + c * 8;
        CP16(sb + FSM_QHI + doff, Qhi + goff);
        CP16(sb + FSM_QLO + doff, Qlo + goff);
    }
    issueKV(0);
    CP_WAIT0();
    __syncthreads();

    const int m0 = wid * 16;
    uint32_t qh[4][4], ql[4][4];
#pragma unroll
    for (int ks = 0; ks < 4; ks++) {
        const uint32_t ra = (uint32_t)((m0 + (lane & 15)) * FPITCH + ks * 32 + (lane >> 4) * 16);
        ldmx4(qh[ks], sb + FSM_QHI + ra);
        ldmx4(ql[ks], sb + FSM_QLO + ra);
    }

    float o[8][4];
#pragma unroll
    for (int i = 0; i < 8; i++)
#pragma unroll
        for (int j = 0; j < 4; j++) o[i][j] = 0.f;
    float mr0 = -1e30f, mr1 = -1e30f, lr0 = 0.f, lr1 = 0.f;

    const int NT = NKV_ / 64;
    for (int kt = 0; kt < NT; kt++) {
        CP_WAIT0();
        __syncthreads();
        if (kt + 1 < NT) issueKV(kt + 1);

        const uint32_t kb = sb + (uint32_t)((kt & 1) * FST);

        float s[8][4];
#pragma unroll
        for (int i = 0; i < 8; i++)
#pragma unroll
            for (int j = 0; j < 4; j++) s[i][j] = 0.f;

        // ---- S = Q K^T, term-major across all 8 accumulators ----
#pragma unroll
        for (int ks = 0; ks < 4; ks++) {
            uint32_t bh[4][4], bl[4][4];
#pragma unroll
            for (int ntp = 0; ntp < 4; ntp++) {
                const uint32_t rb = (uint32_t)((ntp * 16 + (lane & 15)) * FPITCH
                                  + ks * 32 + (lane >> 4) * 16);
                ldmx4(bh[ntp], kb + rb);
                ldmx4(bl[ntp], kb + FT + rb);
            }
            // term 1: qh x bh (8 indep)
#pragma unroll
            for (int ntp = 0; ntp < 4; ntp++)
#pragma unroll
                for (int oo = 0; oo < 2; oo++)
                    mma_bf16(s[ntp * 2 + oo], qh[ks], bh[ntp][oo], bh[ntp][oo + 2]);
            // term 2: qh x bl
#pragma unroll
            for (int ntp = 0; ntp < 4; ntp++)
#pragma unroll
                for (int oo = 0; oo < 2; oo++)
                    mma_bf16(s[ntp * 2 + oo], qh[ks], bl[ntp][oo], bl[ntp][oo + 2]);
            // term 3: ql x bh
#pragma unroll
            for (int ntp = 0; ntp < 4; ntp++)
#pragma unroll
                for (int oo = 0; oo < 2; oo++)
                    mma_bf16(s[ntp * 2 + oo], ql[ks], bh[ntp][oo], bh[ntp][oo + 2]);
        }

        // ---- online softmax ----
        float tm0 = -1e30f, tm1 = -1e30f;
#pragma unroll
        for (int i = 0; i < 8; i++) {
            tm0 = fmaxf(tm0, fmaxf(s[i][0], s[i][1]));
            tm1 = fmaxf(tm1, fmaxf(s[i][2], s[i][3]));
        }
        tm0 = fmaxf(tm0, __shfl_xor_sync(0xffffffffu, tm0, 1));
        tm0 = fmaxf(tm0, __shfl_xor_sync(0xffffffffu, tm0, 2));
        tm1 = fmaxf(tm1, __shfl_xor_sync(0xffffffffu, tm1, 1));
        tm1 = fmaxf(tm1, __shfl_xor_sync(0xffffffffu, tm1, 2));

        const float mn0 = fmaxf(mr0, tm0);
        const float mn1 = fmaxf(mr1, tm1);
        const float cr0 = __expf(mr0 - mn0);
        const float cr1 = __expf(mr1 - mn1);
        mr0 = mn0; mr1 = mn1;

        float ps0 = 0.f, ps1 = 0.f;
#pragma unroll
        for (int i = 0; i < 8; i++) {
            s[i][0] = __expf(s[i][0] - mn0);
            s[i][1] = __expf(s[i][1] - mn0);
            s[i][2] = __expf(s[i][2] - mn1);
            s[i][3] = __expf(s[i][3] - mn1);
            ps0 += s[i][0] + s[i][1];
            ps1 += s[i][2] + s[i][3];
        }
        ps0 += __shfl_xor_sync(0xffffffffu, ps0, 1);
        ps0 += __shfl_xor_sync(0xffffffffu, ps0, 2);
        ps1 += __shfl_xor_sync(0xffffffffu, ps1, 1);
        ps1 += __shfl_xor_sync(0xffffffffu, ps1, 2);
        lr0 = lr0 * cr0 + ps0;
        lr1 = lr1 * cr1 + ps1;

#pragma unroll
        for (int i = 0; i < 8; i++) {
            o[i][0] *= cr0; o[i][1] *= cr0;
            o[i][2] *= cr1; o[i][3] *= cr1;
        }

        // ---- O += P V, term-major across all 8 accumulators ----
#pragma unroll
        for (int ks2 = 0; ks2 < 4; ks2++) {
            const int n0 = 2 * ks2, n1 = 2 * ks2 + 1;
            uint32_t ph[4], pl[4];
            float rv[8];
#pragma unroll
            for (int e = 0; e < 4; e++) {
                const float v0 = s[n0][e], v1 = s[n1][e];
                rv[e]     = v0 - __bfloat162float(__float2bfloat16(v0));
                rv[e + 4] = v1 - __bfloat162float(__float2bfloat16(v1));
            }
            ph[0] = pack_bf16x2(s[n0][0], s[n0][1]);
            ph[1] = pack_bf16x2(s[n0][2], s[n0][3]);
            ph[2] = pack_bf16x2(s[n1][0], s[n1][1]);
            ph[3] = pack_bf16x2(s[n1][2], s[n1][3]);
            pl[0] = pack_bf16x2(rv[0], rv[1]);
            pl[1] = pack_bf16x2(rv[2], rv[3]);
            pl[2] = pack_bf16x2(rv[4], rv[5]);
            pl[3] = pack_bf16x2(rv[6], rv[7]);

            uint32_t vh[4][4], vl[4][4];
#pragma unroll
            for (int ntp = 0; ntp < 4; ntp++) {
                const uint32_t rv2 = (uint32_t)((ks2 * 16 + (lane & 15)) * FPITCH
                                   + ntp * 32 + (lane >> 4) * 16);
                ldmx4t(vh[ntp], kb + 2 * FT + rv2);
                ldmx4t(vl[ntp], kb + 3 * FT + rv2);
            }
            // term 1: ph x vh (8 indep)
#pragma unroll
            for (int ntp = 0; ntp < 4; ntp++)
#pragma unroll
                for (int o2 = 0; o2 < 2; o2++)
                    mma_bf16(o[ntp * 2 + o2], ph, vh[ntp][o2 * 2], vh[ntp][o2 * 2 + 1]);
            // term 2: ph x vl
#pragma unroll
            for (int ntp = 0; ntp < 4; ntp++)
#pragma unroll
                for (int o2 = 0; o2 < 2; o2++)
                    mma_bf16(o[ntp * 2 + o2], ph, vl[ntp][o2 * 2], vl[ntp][o2 * 2 + 1]);
            // term 3: pl x vh
#pragma unroll
            for (int ntp = 0; ntp < 4; ntp++)
#pragma unroll
                for (int o2 = 0; o2 < 2; o2++)
                    mma_bf16(o[ntp * 2 + o2], pl, vh[ntp][o2 * 2], vh[ntp][o2 * 2 + 1]);
        }
    }

    const float inv0 = 1.f / lr0;
    const float inv1 = 1.f / lr1;
    const int r = lane >> 2;
    const long orow = (qrow0 + m0 + r) * D_ + col0;
#pragma unroll
    for (int nt = 0; nt < 8; nt++) {
        const int c = nt * 8 + (lane & 3) * 2;
        const float a0 = o[nt][0] * inv0, a1 = o[nt][1] * inv0;
        const float a2 = o[nt][2] * inv1, a3 = o[nt][3] * inv1;
        const float h0 = __bfloat162float(__float2bfloat16(a0));
        const float h1 = __bfloat162float(__float2bfloat16(a1));
        const float h2 = __bfloat162float(__float2bfloat16(a2));
        const float h3 = __bfloat162float(__float2bfloat16(a3));
        *(uint32_t*)&Ophi[orow + c]           = pack_bf16x2(a0, a1);
        *(uint32_t*)&Ophi[orow + 8 * D_ + c]  = pack_bf16x2(a2, a3);
        *(uint32_t*)&Oplo[orow + c]           = pack_bf16x2(a0 - h0, a1 - h1);
        *(uint32_t*)&Oplo[orow + 8 * D_ + c]  = pack_bf16x2(a2 - h2, a3 - h3);
    }
}

// ===========================================================================
extern "C" void kernel_launch(void* const* d_in, const int* in_sizes, int n_in,
                              void* d_out, int out_size)
{
    const float* q  = (const float*)d_in[0];
    const float* kv = (const float*)d_in[1];
    const float* Wq = (const float*)d_in[2];
    const float* bq = (const float*)d_in[3];
    const float* Wk = (const float*)d_in[4];
    const float* bk = (const float*)d_in[5];
    const float* Wv = (const float*)d_in[6];
    const float* bv = (const float*)d_in[7];
    const float* Wo = (const float*)d_in[8];
    const float* bo = (const float*)d_in[9];
    float* out = (float*)d_out;

    __nv_bfloat16 *qhi, *qlo, *kvhi, *kvlo;
    __nv_bfloat16 *Wqhi, *Wqlo, *Wkhi, *Wklo, *Wvhi, *Wvlo, *Wohi, *Wolo;
    __nv_bfloat16 *Qhi, *Qlo, *Khi, *Klo, *Vhi, *Vlo, *Ophi, *Oplo;
    cudaGetSymbolAddress((void**)&qhi,  g_qhi);
    cudaGetSymbolAddress((void**)&qlo,  g_qlo);
    cudaGetSymbolAddress((void**)&kvhi, g_kvhi);
    cudaGetSymbolAddress((void**)&kvlo, g_kvlo);
    cudaGetSymbolAddress((void**)&Wqhi, g_Wqhi);
    cudaGetSymbolAddress((void**)&Wqlo, g_Wqlo);
    cudaGetSymbolAddress((void**)&Wkhi, g_Wkhi);
    cudaGetSymbolAddress((void**)&Wklo, g_Wklo);
    cudaGetSymbolAddress((void**)&Wvhi, g_Wvhi);
    cudaGetSymbolAddress((void**)&Wvlo, g_Wvlo);
    cudaGetSymbolAddress((void**)&Wohi, g_Wohi);
    cudaGetSymbolAddress((void**)&Wolo, g_Wolo);
    cudaGetSymbolAddress((void**)&Qhi,  g_Qhi);
    cudaGetSymbolAddress((void**)&Qlo,  g_Qlo);
    cudaGetSymbolAddress((void**)&Khi,  g_Khi);
    cudaGetSymbolAddress((void**)&Klo,  g_Klo);
    cudaGetSymbolAddress((void**)&Vhi,  g_Vhi);
    cudaGetSymbolAddress((void**)&Vlo,  g_Vlo);
    cudaGetSymbolAddress((void**)&Ophi, g_Ophi);
    cudaGetSymbolAddress((void**)&Oplo, g_Oplo);

    cudaFuncSetAttribute(gemm_ps<0>, cudaFuncAttributeMaxDynamicSharedMemorySize, SM_TOTAL);
    cudaFuncSetAttribute(gemm_ps<1>, cudaFuncAttributeMaxDynamicSharedMemorySize, SM_TOTAL);
    cudaFuncSetAttribute(flash_mma,  cudaFuncAttributeMaxDynamicSharedMemorySize, FSM_TOTAL);

    const int NQK = B_ * NQ_ * D_;
    const int NW  = D_ * D_;
    split_kernel<<<NQK / 1024, 256>>>(q,  qhi,  qlo);
    split_kernel<<<NQK / 1024, 256>>>(kv, kvhi, kvlo);
    split_kernel<<<NW / 1024, 256>>>(Wq, Wqhi, Wqlo);
    split_kernel<<<NW / 1024, 256>>>(Wk, Wkhi, Wklo);
    split_kernel<<<NW / 1024, 256>>>(Wv, Wvhi, Wvlo);
    split_kernel<<<NW / 1024, 256>>>(Wo, Wohi, Wolo);

    dim3 ggrid(GN / 128, GM / 128);  // (8, 32)

    gemm_ps<1><<<ggrid, 256, SM_TOTAL>>>(qhi,  qlo,  Wqhi, Wqlo, bq, nullptr, Qhi, Qlo, 0.125f);
    gemm_ps<1><<<ggrid, 256, SM_TOTAL>>>(kvhi, kvlo, Wkhi, Wklo, bk, nullptr, Khi, Klo, 1.0f);
    gemm_ps<1><<<ggrid, 256, SM_TOTAL>>>(kvhi, kvlo, Wvhi, Wvlo, bv, nullptr, Vhi, Vlo, 1.0f);

    flash_mma<<<dim3(NQ_ / 64, H_, B_), 128, FSM_TOTAL>>>(Qhi, Qlo, Khi, Klo, Vhi, Vlo, Ophi, Oplo);

    gemm_ps<0><<<ggrid, 256, SM_TOTAL>>>(Ophi, Oplo, Wohi, Wolo, bo, out, nullptr, nullptr, 1.0f);
}

// round 15
// speedup vs baseline: 2.2756x; 2.2756x over previous
#include <cuda_runtime.h>
#include <cuda_fp16.h>
#include <math.h>
#include <stdint.h>

#define B_   2
#define NQ_  2048
#define NKV_ 2048
#define D_   1024
#define H_   16
#define DH_  64

// ---- Scratch (allocation-free) ----
// A-side split inputs (fp16 hi/lo), B-side single-rounded weights
__device__ __half g_qhi[B_ * NQ_ * D_],  g_qlo[B_ * NQ_ * D_];
__device__ __half g_kvhi[B_ * NKV_ * D_], g_kvlo[B_ * NKV_ * D_];
__device__ __half g_Wq[D_ * D_], g_Wk[D_ * D_], g_Wv[D_ * D_], g_Wo[D_ * D_];
// Projection outputs: Q split (A-side of QK), K/V single (B-side)
__device__ __half g_Qhi[B_ * NQ_ * D_], g_Qlo[B_ * NQ_ * D_];
__device__ __half g_K[B_ * NKV_ * D_];
__device__ __half g_V[B_ * NKV_ * D_];
// Flash output split (A-side of O-proj)
__device__ __half g_Ophi[B_ * NQ_ * D_], g_Oplo[B_ * NQ_ * D_];

__device__ __forceinline__ uint32_t smem_u32(const void* p) {
    uint32_t a;
    asm("{ .reg .u64 t; cvta.to.shared.u64 t, %1; cvt.u32.u64 %0, t; }"
        : "=r"(a) : "l"(p));
    return a;
}

__device__ __forceinline__ void mma_f16(float* d, const uint32_t* a,
                                        uint32_t b0, uint32_t b1) {
    asm volatile(
        "mma.sync.aligned.m16n8k16.row.col.f32.f16.f16.f32 "
        "{%0,%1,%2,%3}, {%4,%5,%6,%7}, {%8,%9}, {%0,%1,%2,%3};"
        : "+f"(d[0]), "+f"(d[1]), "+f"(d[2]), "+f"(d[3])
        : "r"(a[0]), "r"(a[1]), "r"(a[2]), "r"(a[3]), "r"(b0), "r"(b1));
}

__device__ __forceinline__ void ldmx4(uint32_t* r, uint32_t addr) {
    asm volatile(
        "ldmatrix.sync.aligned.m8n8.x4.shared.b16 {%0,%1,%2,%3}, [%4];"
        : "=r"(r[0]), "=r"(r[1]), "=r"(r[2]), "=r"(r[3]) : "r"(addr));
}

__device__ __forceinline__ void ldmx4t(uint32_t* r, uint32_t addr) {
    asm volatile(
        "ldmatrix.sync.aligned.m8n8.x4.trans.shared.b16 {%0,%1,%2,%3}, [%4];"
        : "=r"(r[0]), "=r"(r[1]), "=r"(r[2]), "=r"(r[3]) : "r"(addr));
}

__device__ __forceinline__ uint32_t pack_h2(float a, float b) {
    __half2 h = __floats2half2_rn(a, b);   // low = a, high = b
    return *(uint32_t*)&h;
}

#define CP16(dst, src) \
    asm volatile("cp.async.cg.shared.global [%0], [%1], 16;" :: "r"(dst), "l"(src))
#define CP_COMMIT() asm volatile("cp.async.commit_group;" ::: "memory")
#define CP_WAIT0()  asm volatile("cp.async.wait_group 0;" ::: "memory")

// ===========================================================================
// split2: fp32 -> fp16 hi/lo (hi = h(x), lo = h(x - hi))
// ===========================================================================
__global__ __launch_bounds__(256) void split2_kernel(
    const float* __restrict__ x, __half* __restrict__ hi, __half* __restrict__ lo)
{
    const int i = (blockIdx.x * 256 + threadIdx.x) * 4;
    const float4 v = *(const float4*)(x + i);
    const __half h0 = __float2half_rn(v.x), h1 = __float2half_rn(v.y);
    const __half h2 = __float2half_rn(v.z), h3 = __float2half_rn(v.w);
    uint2 hv, lv;
    hv.x = pack_h2(v.x, v.y);  // packs rounded halves of v.x,v.y
    hv.y = pack_h2(v.z, v.w);
    lv.x = pack_h2(v.x - __half2float(h0), v.y - __half2float(h1));
    lv.y = pack_h2(v.z - __half2float(h2), v.w - __half2float(h3));
    *(uint2*)(hi + i) = hv;
    *(uint2*)(lo + i) = lv;
}

// round1: fp32 -> fp16 single
__global__ __launch_bounds__(256) void round1_kernel(
    const float* __restrict__ x, __half* __restrict__ y)
{
    const int i = (blockIdx.x * 256 + threadIdx.x) * 4;
    const float4 v = *(const float4*)(x + i);
    uint2 o;
    o.x = pack_h2(v.x, v.y);
    o.y = pack_h2(v.z, v.w);
    *(uint2*)(y + i) = o;
}

// ===========================================================================
// fp16x2 asymmetric HMMA GEMM: C = A[M,K] @ W[N,K]^T + bias.
// A pre-split fp16 (hi,lo); W single fp16. 2 MMAs per product.
// CTA 128x128, K-chunk 64, 512 threads (4x4 warps, warp tile 32x32),
// double-buffered cp.async. 3 smem tiles/stage (Ahi, Alo, W).
// OUTMODE 0: fp32 out. 1: split fp16 out. 2: single fp16 out.
// ===========================================================================
#define GM 4096
#define GN 1024
#define GK 1024
#define GPITCH 144
#define GT  (128 * GPITCH)       // 18432 per tile
#define GST (3 * GT)             // 55296 per stage
#define SM_TOTAL (2 * GST)       // 110592

template <int OUTMODE>
__global__ __launch_bounds__(512) void gemm_ps(
    const __half* __restrict__ Ahi, const __half* __restrict__ Alo,
    const __half* __restrict__ W,
    const float* __restrict__ bias, float* __restrict__ C,
    __half* __restrict__ Chi, __half* __restrict__ Clo)
{
    extern __shared__ char smem[];
    const uint32_t sb = smem_u32(smem);
    const int tid  = threadIdx.x;
    const int wid  = tid >> 5;
    const int lane = tid & 31;
    const int bm = blockIdx.y * 128;
    const int bn = blockIdx.x * 128;
    const int warp_m = wid >> 2;         // 0..3
    const int warp_n = wid & 3;          // 0..3

    float acc[2][4][4];
#pragma unroll
    for (int i = 0; i < 2; i++)
#pragma unroll
        for (int j = 0; j < 4; j++)
#pragma unroll
            for (int k = 0; k < 4; k++) acc[i][j][k] = 0.f;

    auto issue_chunk = [&](int chunk) {
        const uint32_t base = sb + (uint32_t)((chunk & 1) * GST);
        const int kc = chunk * 64;
#pragma unroll
        for (int it = 0; it < 6; it++) {
            const int t   = it >> 1;                // 0:Ahi 1:Alo 2:W
            const int sub = (it & 1) * 512 + tid;   // 0..1023
            const int r   = sub >> 3;               // 0..127
            const int c   = sub & 7;                // 16B chunk
            const uint32_t dst = base + (uint32_t)(t * GT + r * GPITCH + c * 16);
            const __half* src;
            if      (t == 0) src = Ahi + (long)(bm + r) * GK + kc + c * 8;
            else if (t == 1) src = Alo + (long)(bm + r) * GK + kc + c * 8;
            else             src = W   + (long)(bn + r) * GK + kc + c * 8;
            CP16(dst, src);
        }
        CP_COMMIT();
    };

    issue_chunk(0);

    for (int chunk = 0; chunk < GK / 64; chunk++) {
        CP_WAIT0();
        __syncthreads();
        if (chunk + 1 < GK / 64) issue_chunk(chunk + 1);

        const uint32_t base = sb + (uint32_t)((chunk & 1) * GST);
#pragma unroll
        for (int ks = 0; ks < 4; ks++) {
            uint32_t ah[2][4], al[2][4];
#pragma unroll
            for (int mt = 0; mt < 2; mt++) {
                const uint32_t ra = (uint32_t)((warp_m * 32 + mt * 16 + (lane & 15)) * GPITCH
                                  + ks * 32 + (lane >> 4) * 16);
                ldmx4(ah[mt], base + ra);
                ldmx4(al[mt], base + GT + ra);
            }
            uint32_t bh[2][4];
#pragma unroll
            for (int nt2 = 0; nt2 < 2; nt2++) {
                const uint32_t rb = (uint32_t)((warp_n * 32 + nt2 * 16 + (lane & 15)) * GPITCH
                                  + ks * 32 + (lane >> 4) * 16);
                ldmx4(bh[nt2], base + 2 * GT + rb);
            }
#pragma unroll
            for (int mt = 0; mt < 2; mt++) {
#pragma unroll
                for (int nt = 0; nt < 4; nt++) {
                    const int g = nt >> 1, o = nt & 1;
                    mma_f16(acc[mt][nt], ah[mt], bh[g][o], bh[g][o + 2]);
                    mma_f16(acc[mt][nt], al[mt], bh[g][o], bh[g][o + 2]);
                }
            }
        }
    }

    const int rq = lane >> 2;
    const int cq = (lane & 3) * 2;
#pragma unroll
    for (int mt = 0; mt < 2; mt++) {
        const int r0 = bm + warp_m * 32 + mt * 16 + rq;
#pragma unroll
        for (int nt = 0; nt < 4; nt++) {
            const int c = bn + warp_n * 32 + nt * 8 + cq;
            const float2 bv = *(const float2*)&bias[c];
            const float v0 = acc[mt][nt][0] + bv.x;
            const float v1 = acc[mt][nt][1] + bv.y;
            const float v2 = acc[mt][nt][2] + bv.x;
            const float v3 = acc[mt][nt][3] + bv.y;
            if (OUTMODE == 0) {
                *(float2*)&C[(long)r0 * GN + c]       = make_float2(v0, v1);
                *(float2*)&C[(long)(r0 + 8) * GN + c] = make_float2(v2, v3);
            } else if (OUTMODE == 2) {
                *(uint32_t*)&Chi[(long)r0 * GN + c]       = pack_h2(v0, v1);
                *(uint32_t*)&Chi[(long)(r0 + 8) * GN + c] = pack_h2(v2, v3);
            } else {
                const float h0 = __half2float(__float2half_rn(v0));
                const float h1 = __half2float(__float2half_rn(v1));
                const float h2 = __half2float(__float2half_rn(v2));
                const float h3 = __half2float(__float2half_rn(v3));
                *(uint32_t*)&Chi[(long)r0 * GN + c]       = pack_h2(v0, v1);
                *(uint32_t*)&Chi[(long)(r0 + 8) * GN + c] = pack_h2(v2, v3);
                *(uint32_t*)&Clo[(long)r0 * GN + c]       = pack_h2(v0 - h0, v1 - h1);
                *(uint32_t*)&Clo[(long)(r0 + 8) * GN + c] = pack_h2(v2 - h2, v3 - h3);
            }
        }
    }
}

// ===========================================================================
// fp16x2 HMMA flash attention. Q split (A-side), K/V single fp16 (B-side).
// 64 q-rows, 4 warps; KV tiles of 64 double-buffered (2 tiles/stage);
// Q overlaid on stage 1. 1/sqrt(d) applied at softmax; P scaled x256 for
// split (folded into 1/l). Output split fp16.
// ===========================================================================
#define FPITCH 144
#define FT  (64 * FPITCH)          // 9216
#define FST (2 * FT)               // 18432 per stage (K, V)
#define FSM_QHI (FST)              // Q inside stage 1
#define FSM_QLO (FST + FT)
#define FSM_TOTAL (2 * FST)        // 36864

__global__ __launch_bounds__(128) void flash_mma(
    const __half* __restrict__ Qhi, const __half* __restrict__ Qlo,
    const __half* __restrict__ Ks,  const __half* __restrict__ Vs,
    __half* __restrict__ Ophi, __half* __restrict__ Oplo)
{
    extern __shared__ char smem[];
    const uint32_t sb = smem_u32(smem);
    const int tid  = threadIdx.x;
    const int wid  = tid >> 5;
    const int lane = tid & 31;
    const int qt = blockIdx.x, h = blockIdx.y, b = blockIdx.z;

    const long qrow0 = (long)b * NQ_ + qt * 64;
    const long krow0 = (long)b * NKV_;
    const int  col0  = h * DH_;

    auto issueKV = [&](int kt) {
        const uint32_t base = sb + (uint32_t)((kt & 1) * FST);
#pragma unroll
        for (int it = 0; it < 4; it++) {
            const int idx = it * 128 + tid;
            const int r = idx >> 3, c = idx & 7;
            const uint32_t doff = (uint32_t)(r * FPITCH + c * 16);
            const long goff = (krow0 + kt * 64 + r) * D_ + col0 + c * 8;
            CP16(base + doff,      Ks + goff);
            CP16(base + FT + doff, Vs + goff);
        }
        CP_COMMIT();
    };

#pragma unroll
    for (int it = 0; it < 4; it++) {
        const int idx = it * 128 + tid;
        const int r = idx >> 3, c = idx & 7;
        const uint32_t doff = (uint32_t)(r * FPITCH + c * 16);
        const long goff = (qrow0 + r) * D_ + col0 + c * 8;
        CP16(sb + FSM_QHI + doff, Qhi + goff);
        CP16(sb + FSM_QLO + doff, Qlo + goff);
    }
    issueKV(0);
    CP_WAIT0();
    __syncthreads();

    const int m0 = wid * 16;
    uint32_t qh[4][4], ql[4][4];
#pragma unroll
    for (int ks = 0; ks < 4; ks++) {
        const uint32_t ra = (uint32_t)((m0 + (lane & 15)) * FPITCH + ks * 32 + (lane >> 4) * 16);
        ldmx4(qh[ks], sb + FSM_QHI + ra);
        ldmx4(ql[ks], sb + FSM_QLO + ra);
    }

    float o[8][4];
#pragma unroll
    for (int i = 0; i < 8; i++)
#pragma unroll
        for (int j = 0; j < 4; j++) o[i][j] = 0.f;
    float mr0 = -1e30f, mr1 = -1e30f, lr0 = 0.f, lr1 = 0.f;

    const int NT = NKV_ / 64;
    for (int kt = 0; kt < NT; kt++) {
        CP_WAIT0();
        __syncthreads();
        if (kt + 1 < NT) issueKV(kt + 1);

        const uint32_t kb = sb + (uint32_t)((kt & 1) * FST);

        float s[8][4];
#pragma unroll
        for (int i = 0; i < 8; i++)
#pragma unroll
            for (int j = 0; j < 4; j++) s[i][j] = 0.f;

        // ---- S = Q K^T (2-term, Q-side split) ----
#pragma unroll
        for (int ks = 0; ks < 4; ks++) {
#pragma unroll
            for (int ntp = 0; ntp < 4; ntp++) {
                const uint32_t rb = (uint32_t)((ntp * 16 + (lane & 15)) * FPITCH
                                  + ks * 32 + (lane >> 4) * 16);
                uint32_t bh[4];
                ldmx4(bh, kb + rb);
#pragma unroll
                for (int oo = 0; oo < 2; oo++) {
                    float* d = s[ntp * 2 + oo];
                    mma_f16(d, qh[ks], bh[oo], bh[oo + 2]);
                    mma_f16(d, ql[ks], bh[oo], bh[oo + 2]);
                }
            }
        }

        // ---- scale + online softmax ----
#pragma unroll
        for (int i = 0; i < 8; i++)
#pragma unroll
            for (int j = 0; j < 4; j++) s[i][j] *= 0.125f;

        float tm0 = -1e30f, tm1 = -1e30f;
#pragma unroll
        for (int i = 0; i < 8; i++) {
            tm0 = fmaxf(tm0, fmaxf(s[i][0], s[i][1]));
            tm1 = fmaxf(tm1, fmaxf(s[i][2], s[i][3]));
        }
        tm0 = fmaxf(tm0, __shfl_xor_sync(0xffffffffu, tm0, 1));
        tm0 = fmaxf(tm0, __shfl_xor_sync(0xffffffffu, tm0, 2));
        tm1 = fmaxf(tm1, __shfl_xor_sync(0xffffffffu, tm1, 1));
        tm1 = fmaxf(tm1, __shfl_xor_sync(0xffffffffu, tm1, 2));

        const float mn0 = fmaxf(mr0, tm0);
        const float mn1 = fmaxf(mr1, tm1);
        const float cr0 = __expf(mr0 - mn0);
        const float cr1 = __expf(mr1 - mn1);
        mr0 = mn0; mr1 = mn1;

        float ps0 = 0.f, ps1 = 0.f;
#pragma unroll
        for (int i = 0; i < 8; i++) {
            s[i][0] = __expf(s[i][0] - mn0);
            s[i][1] = __expf(s[i][1] - mn0);
            s[i][2] = __expf(s[i][2] - mn1);
            s[i][3] = __expf(s[i][3] - mn1);
            ps0 += s[i][0] + s[i][1];
            ps1 += s[i][2] + s[i][3];
        }
        ps0 += __shfl_xor_sync(0xffffffffu, ps0, 1);
        ps0 += __shfl_xor_sync(0xffffffffu, ps0, 2);
        ps1 += __shfl_xor_sync(0xffffffffu, ps1, 1);
        ps1 += __shfl_xor_sync(0xffffffffu, ps1, 2);
        lr0 = lr0 * cr0 + ps0;
        lr1 = lr1 * cr1 + ps1;

#pragma unroll
        for (int i = 0; i < 8; i++) {
            o[i][0] *= cr0; o[i][1] *= cr0;
            o[i][2] *= cr1; o[i][3] *= cr1;
        }

        // ---- O += (256*P) V  (2-term, P-side split; 256 folded into 1/l) ----
#pragma unroll
        for (int ks2 = 0; ks2 < 4; ks2++) {
            const int n0 = 2 * ks2, n1 = 2 * ks2 + 1;
            float pv[8];
#pragma unroll
            for (int e = 0; e < 4; e++) {
                pv[e]     = s[n0][e] * 256.f;
                pv[e + 4] = s[n1][e] * 256.f;
            }
            uint32_t ph[4], pl[4];
            ph[0] = pack_h2(pv[0], pv[1]);
            ph[1] = pack_h2(pv[2], pv[3]);
            ph[2] = pack_h2(pv[4], pv[5]);
            ph[3] = pack_h2(pv[6], pv[7]);
            float pr[8];
#pragma unroll
            for (int e = 0; e < 8; e++)
                pr[e] = pv[e] - __half2float(__float2half_rn(pv[e]));
            pl[0] = pack_h2(pr[0], pr[1]);
            pl[1] = pack_h2(pr[2], pr[3]);
            pl[2] = pack_h2(pr[4], pr[5]);
            pl[3] = pack_h2(pr[6], pr[7]);

#pragma unroll
            for (int ntp = 0; ntp < 4; ntp++) {
                const uint32_t rv2 = (uint32_t)((ks2 * 16 + (lane & 15)) * FPITCH
                                   + ntp * 32 + (lane >> 4) * 16);
                uint32_t vh[4];
                ldmx4t(vh, kb + FT + rv2);
#pragma unroll
                for (int o2 = 0; o2 < 2; o2++) {
                    float* d = o[ntp * 2 + o2];
                    mma_f16(d, ph, vh[o2 * 2], vh[o2 * 2 + 1]);
                    mma_f16(d, pl, vh[o2 * 2], vh[o2 * 2 + 1]);
                }
            }
        }
    }

    // ---- finalize: normalize (1/(256*l)) + split-store fp16 hi/lo ----
    const float inv0 = 1.f / (256.f * lr0);
    const float inv1 = 1.f / (256.f * lr1);
    const int r = lane >> 2;
    const long orow = (qrow0 + m0 + r) * D_ + col0;
#pragma unroll
    for (int nt = 0; nt < 8; nt++) {
        const int c = nt * 8 + (lane & 3) * 2;
        const float a0 = o[nt][0] * inv0, a1 = o[nt][1] * inv0;
        const float a2 = o[nt][2] * inv1, a3 = o[nt][3] * inv1;
        const float h0 = __half2float(__float2half_rn(a0));
        const float h1 = __half2float(__float2half_rn(a1));
        const float h2 = __half2float(__float2half_rn(a2));
        const float h3 = __half2float(__float2half_rn(a3));
        *(uint32_t*)&Ophi[orow + c]          = pack_h2(a0, a1);
        *(uint32_t*)&Ophi[orow + 8 * D_ + c] = pack_h2(a2, a3);
        *(uint32_t*)&Oplo[orow + c]          = pack_h2(a0 - h0, a1 - h1);
        *(uint32_t*)&Oplo[orow + 8 * D_ + c] = pack_h2(a2 - h2, a3 - h3);
    }
}

// ===========================================================================
extern "C" void kernel_launch(void* const* d_in, const int* in_sizes, int n_in,
                              void* d_out, int out_size)
{
    const float* q  = (const float*)d_in[0];
    const float* kv = (const float*)d_in[1];
    const float* Wq = (const float*)d_in[2];
    const float* bq = (const float*)d_in[3];
    const float* Wk = (const float*)d_in[4];
    const float* bk = (const float*)d_in[5];
    const float* Wv = (const float*)d_in[6];
    const float* bv = (const float*)d_in[7];
    const float* Wo = (const float*)d_in[8];
    const float* bo = (const float*)d_in[9];
    float* out = (float*)d_out;

    __half *qhi, *qlo, *kvhi, *kvlo, *Wqh, *Wkh, *Wvh, *Woh;
    __half *Qhi, *Qlo, *Kh, *Vh, *Ophi, *Oplo;
    cudaGetSymbolAddress((void**)&qhi,  g_qhi);
    cudaGetSymbolAddress((void**)&qlo,  g_qlo);
    cudaGetSymbolAddress((void**)&kvhi, g_kvhi);
    cudaGetSymbolAddress((void**)&kvlo, g_kvlo);
    cudaGetSymbolAddress((void**)&Wqh,  g_Wq);
    cudaGetSymbolAddress((void**)&Wkh,  g_Wk);
    cudaGetSymbolAddress((void**)&Wvh,  g_Wv);
    cudaGetSymbolAddress((void**)&Woh,  g_Wo);
    cudaGetSymbolAddress((void**)&Qhi,  g_Qhi);
    cudaGetSymbolAddress((void**)&Qlo,  g_Qlo);
    cudaGetSymbolAddress((void**)&Kh,   g_K);
    cudaGetSymbolAddress((void**)&Vh,   g_V);
    cudaGetSymbolAddress((void**)&Ophi, g_Ophi);
    cudaGetSymbolAddress((void**)&Oplo, g_Oplo);

    cudaFuncSetAttribute(gemm_ps<0>, cudaFuncAttributeMaxDynamicSharedMemorySize, SM_TOTAL);
    cudaFuncSetAttribute(gemm_ps<1>, cudaFuncAttributeMaxDynamicSharedMemorySize, SM_TOTAL);
    cudaFuncSetAttribute(gemm_ps<2>, cudaFuncAttributeMaxDynamicSharedMemorySize, SM_TOTAL);
    cudaFuncSetAttribute(flash_mma,  cudaFuncAttributeMaxDynamicSharedMemorySize, FSM_TOTAL);

    const int NQK = B_ * NQ_ * D_;     // 4M
    const int NW  = D_ * D_;           // 1M
    split2_kernel<<<NQK / 1024, 256>>>(q,  qhi,  qlo);
    split2_kernel<<<NQK / 1024, 256>>>(kv, kvhi, kvlo);
    round1_kernel<<<NW / 1024, 256>>>(Wq, Wqh);
    round1_kernel<<<NW / 1024, 256>>>(Wk, Wkh);
    round1_kernel<<<NW / 1024, 256>>>(Wv, Wvh);
    round1_kernel<<<NW / 1024, 256>>>(Wo, Woh);

    dim3 ggrid(GN / 128, GM / 128);  // (8, 32)

    gemm_ps<1><<<ggrid, 512, SM_TOTAL>>>(qhi,  qlo,  Wqh, bq, nullptr, Qhi, Qlo);
    gemm_ps<2><<<ggrid, 512, SM_TOTAL>>>(kvhi, kvlo, Wkh, bk, nullptr, Kh, nullptr);
    gemm_ps<2><<<ggrid, 512, SM_TOTAL>>>(kvhi, kvlo, Wvh, bv, nullptr, Vh, nullptr);

    flash_mma<<<dim3(NQ_ / 64, H_, B_), 128, FSM_TOTAL>>>(Qhi, Qlo, Kh, Vh, Ophi, Oplo);

    gemm_ps<0><<<ggrid, 512, SM_TOTAL>>>(Ophi, Oplo, Woh, bo, out, nullptr, nullptr);
}

// round 16
// speedup vs baseline: 2.5969x; 1.1412x over previous
#include <cuda_runtime.h>
#include <cuda_fp16.h>
#include <math.h>
#include <stdint.h>

#define B_   2
#define NQ_  2048
#define NKV_ 2048
#define D_   1024
#define H_   16
#define DH_  64

// ---- Scratch (allocation-free) ----
__device__ __half g_qhi[B_ * NQ_ * D_],  g_qlo[B_ * NQ_ * D_];
__device__ __half g_kvhi[B_ * NKV_ * D_], g_kvlo[B_ * NKV_ * D_];
__device__ __half g_Wq[D_ * D_], g_Wk[D_ * D_], g_Wv[D_ * D_], g_Wo[D_ * D_];
__device__ __half g_Qhi[B_ * NQ_ * D_], g_Qlo[B_ * NQ_ * D_];
__device__ __half g_K[B_ * NKV_ * D_];
__device__ __half g_V[B_ * NKV_ * D_];
__device__ __half g_O[B_ * NQ_ * D_];    // single fp16 attention output

__device__ __forceinline__ uint32_t smem_u32(const void* p) {
    uint32_t a;
    asm("{ .reg .u64 t; cvta.to.shared.u64 t, %1; cvt.u32.u64 %0, t; }"
        : "=r"(a) : "l"(p));
    return a;
}

__device__ __forceinline__ void mma_f16(float* d, const uint32_t* a,
                                        uint32_t b0, uint32_t b1) {
    asm volatile(
        "mma.sync.aligned.m16n8k16.row.col.f32.f16.f16.f32 "
        "{%0,%1,%2,%3}, {%4,%5,%6,%7}, {%8,%9}, {%0,%1,%2,%3};"
        : "+f"(d[0]), "+f"(d[1]), "+f"(d[2]), "+f"(d[3])
        : "r"(a[0]), "r"(a[1]), "r"(a[2]), "r"(a[3]), "r"(b0), "r"(b1));
}

__device__ __forceinline__ void ldmx4(uint32_t* r, uint32_t addr) {
    asm volatile(
        "ldmatrix.sync.aligned.m8n8.x4.shared.b16 {%0,%1,%2,%3}, [%4];"
        : "=r"(r[0]), "=r"(r[1]), "=r"(r[2]), "=r"(r[3]) : "r"(addr));
}

__device__ __forceinline__ void ldmx4t(uint32_t* r, uint32_t addr) {
    asm volatile(
        "ldmatrix.sync.aligned.m8n8.x4.trans.shared.b16 {%0,%1,%2,%3}, [%4];"
        : "=r"(r[0]), "=r"(r[1]), "=r"(r[2]), "=r"(r[3]) : "r"(addr));
}

__device__ __forceinline__ uint32_t pack_h2(float a, float b) {
    __half2 h = __floats2half2_rn(a, b);
    return *(uint32_t*)&h;
}

#define CP16(dst, src) \
    asm volatile("cp.async.cg.shared.global [%0], [%1], 16;" :: "r"(dst), "l"(src))
#define CP_COMMIT() asm volatile("cp.async.commit_group;" ::: "memory")
#define CP_WAIT0()  asm volatile("cp.async.wait_group 0;" ::: "memory")

// ===========================================================================
// split2: fp32 -> fp16 hi/lo.   round1: fp32 -> fp16.
// ===========================================================================
__global__ __launch_bounds__(256) void split2_kernel(
    const float* __restrict__ x, __half* __restrict__ hi, __half* __restrict__ lo)
{
    const int i = (blockIdx.x * 256 + threadIdx.x) * 4;
    const float4 v = *(const float4*)(x + i);
    const __half h0 = __float2half_rn(v.x), h1 = __float2half_rn(v.y);
    const __half h2 = __float2half_rn(v.z), h3 = __float2half_rn(v.w);
    uint2 hv, lv;
    hv.x = pack_h2(v.x, v.y);
    hv.y = pack_h2(v.z, v.w);
    lv.x = pack_h2(v.x - __half2float(h0), v.y - __half2float(h1));
    lv.y = pack_h2(v.z - __half2float(h2), v.w - __half2float(h3));
    *(uint2*)(hi + i) = hv;
    *(uint2*)(lo + i) = lv;
}

__global__ __launch_bounds__(256) void round1_kernel(
    const float* __restrict__ x, __half* __restrict__ y)
{
    const int i = (blockIdx.x * 256 + threadIdx.x) * 4;
    const float4 v = *(const float4*)(x + i);
    uint2 o;
    o.x = pack_h2(v.x, v.y);
    o.y = pack_h2(v.z, v.w);
    *(uint2*)(y + i) = o;
}

// ===========================================================================
// fp16 HMMA GEMM: C = A[M,K] @ W[N,K]^T + bias.
// ATERMS=2: A split (hi,lo), 2 MMAs/product. ATERMS=1: A single, 1 MMA.
// CTA 128x128, K-chunk 64, 512 threads (4x4 warps, warp tile 32x32),
// double-buffered cp.async. OUTMODE 0: fp32. 1: split fp16. 2: single fp16.
// ===========================================================================
#define GM 4096
#define GN 1024
#define GK 1024
#define GPITCH 144
#define GT  (128 * GPITCH)             // 18432 per tile

template <int ATERMS, int OUTMODE>
__global__ __launch_bounds__(512) void gemm_ps(
    const __half* __restrict__ Ahi, const __half* __restrict__ Alo,
    const __half* __restrict__ W,
    const float* __restrict__ bias, float* __restrict__ C,
    __half* __restrict__ Chi, __half* __restrict__ Clo)
{
    constexpr int NTILES = ATERMS + 1;       // A tiles + W tile
    constexpr int GST = NTILES * GT;
    extern __shared__ char smem[];
    const uint32_t sb = smem_u32(smem);
    const int tid  = threadIdx.x;
    const int wid  = tid >> 5;
    const int lane = tid & 31;
    const int bm = blockIdx.y * 128;
    const int bn = blockIdx.x * 128;
    const int warp_m = wid >> 2;
    const int warp_n = wid & 3;

    float acc[2][4][4];
#pragma unroll
    for (int i = 0; i < 2; i++)
#pragma unroll
        for (int j = 0; j < 4; j++)
#pragma unroll
            for (int k = 0; k < 4; k++) acc[i][j][k] = 0.f;

    auto issue_chunk = [&](int chunk) {
        const uint32_t base = sb + (uint32_t)((chunk & 1) * GST);
        const int kc = chunk * 64;
#pragma unroll
        for (int it = 0; it < 2 * NTILES; it++) {
            const int t   = it >> 1;                // tile index
            const int sub = (it & 1) * 512 + tid;   // 0..1023
            const int r   = sub >> 3;
            const int c   = sub & 7;
            const uint32_t dst = base + (uint32_t)(t * GT + r * GPITCH + c * 16);
            const __half* src;
            if (t == 0)                 src = Ahi + (long)(bm + r) * GK + kc + c * 8;
            else if (ATERMS == 2 && t == 1) src = Alo + (long)(bm + r) * GK + kc + c * 8;
            else                        src = W   + (long)(bn + r) * GK + kc + c * 8;
            CP16(dst, src);
        }
        CP_COMMIT();
    };

    issue_chunk(0);

    for (int chunk = 0; chunk < GK / 64; chunk++) {
        CP_WAIT0();
        __syncthreads();
        if (chunk + 1 < GK / 64) issue_chunk(chunk + 1);

        const uint32_t base = sb + (uint32_t)((chunk & 1) * GST);
#pragma unroll
        for (int ks = 0; ks < 4; ks++) {
            uint32_t ah[2][4], al[2][4];
#pragma unroll
            for (int mt = 0; mt < 2; mt++) {
                const uint32_t ra = (uint32_t)((warp_m * 32 + mt * 16 + (lane & 15)) * GPITCH
                                  + ks * 32 + (lane >> 4) * 16);
                ldmx4(ah[mt], base + ra);
                if (ATERMS == 2) ldmx4(al[mt], base + GT + ra);
            }
            uint32_t bh[2][4];
#pragma unroll
            for (int nt2 = 0; nt2 < 2; nt2++) {
                const uint32_t rb = (uint32_t)((warp_n * 32 + nt2 * 16 + (lane & 15)) * GPITCH
                                  + ks * 32 + (lane >> 4) * 16);
                ldmx4(bh[nt2], base + (NTILES - 1) * GT + rb);
            }
#pragma unroll
            for (int mt = 0; mt < 2; mt++) {
#pragma unroll
                for (int nt = 0; nt < 4; nt++) {
                    const int g = nt >> 1, o = nt & 1;
                    mma_f16(acc[mt][nt], ah[mt], bh[g][o], bh[g][o + 2]);
                    if (ATERMS == 2)
                        mma_f16(acc[mt][nt], al[mt], bh[g][o], bh[g][o + 2]);
                }
            }
        }
    }

    const int rq = lane >> 2;
    const int cq = (lane & 3) * 2;
#pragma unroll
    for (int mt = 0; mt < 2; mt++) {
        const int r0 = bm + warp_m * 32 + mt * 16 + rq;
#pragma unroll
        for (int nt = 0; nt < 4; nt++) {
            const int c = bn + warp_n * 32 + nt * 8 + cq;
            const float2 bv = *(const float2*)&bias[c];
            const float v0 = acc[mt][nt][0] + bv.x;
            const float v1 = acc[mt][nt][1] + bv.y;
            const float v2 = acc[mt][nt][2] + bv.x;
            const float v3 = acc[mt][nt][3] + bv.y;
            if (OUTMODE == 0) {
                *(float2*)&C[(long)r0 * GN + c]       = make_float2(v0, v1);
                *(float2*)&C[(long)(r0 + 8) * GN + c] = make_float2(v2, v3);
            } else if (OUTMODE == 2) {
                *(uint32_t*)&Chi[(long)r0 * GN + c]       = pack_h2(v0, v1);
                *(uint32_t*)&Chi[(long)(r0 + 8) * GN + c] = pack_h2(v2, v3);
            } else {
                const float h0 = __half2float(__float2half_rn(v0));
                const float h1 = __half2float(__float2half_rn(v1));
                const float h2 = __half2float(__float2half_rn(v2));
                const float h3 = __half2float(__float2half_rn(v3));
                *(uint32_t*)&Chi[(long)r0 * GN + c]       = pack_h2(v0, v1);
                *(uint32_t*)&Chi[(long)(r0 + 8) * GN + c] = pack_h2(v2, v3);
                *(uint32_t*)&Clo[(long)r0 * GN + c]       = pack_h2(v0 - h0, v1 - h1);
                *(uint32_t*)&Clo[(long)(r0 + 8) * GN + c] = pack_h2(v2 - h2, v3 - h3);
            }
        }
    }
}

// ===========================================================================
// fp16 HMMA flash attention. Q split (2-term QK), K/V single fp16,
// P single fp16 x256 (1-term PV). Output single fp16.
// 64 q-rows, 4 warps; KV tiles of 64 double-buffered; Q overlaid on stage 1.
// ===========================================================================
#define FPITCH 144
#define FT  (64 * FPITCH)          // 9216
#define FST (2 * FT)               // 18432 per stage (K, V)
#define FSM_QHI (FST)
#define FSM_QLO (FST + FT)
#define FSM_TOTAL (2 * FST)        // 36864

__global__ __launch_bounds__(128) void flash_mma(
    const __half* __restrict__ Qhi, const __half* __restrict__ Qlo,
    const __half* __restrict__ Ks,  const __half* __restrict__ Vs,
    __half* __restrict__ O)
{
    extern __shared__ char smem[];
    const uint32_t sb = smem_u32(smem);
    const int tid  = threadIdx.x;
    const int wid  = tid >> 5;
    const int lane = tid & 31;
    const int qt = blockIdx.x, h = blockIdx.y, b = blockIdx.z;

    const long qrow0 = (long)b * NQ_ + qt * 64;
    const long krow0 = (long)b * NKV_;
    const int  col0  = h * DH_;

    auto issueKV = [&](int kt) {
        const uint32_t base = sb + (uint32_t)((kt & 1) * FST);
#pragma unroll
        for (int it = 0; it < 4; it++) {
            const int idx = it * 128 + tid;
            const int r = idx >> 3, c = idx & 7;
            const uint32_t doff = (uint32_t)(r * FPITCH + c * 16);
            const long goff = (krow0 + kt * 64 + r) * D_ + col0 + c * 8;
            CP16(base + doff,      Ks + goff);
            CP16(base + FT + doff, Vs + goff);
        }
        CP_COMMIT();
    };

#pragma unroll
    for (int it = 0; it < 4; it++) {
        const int idx = it * 128 + tid;
        const int r = idx >> 3, c = idx & 7;
        const uint32_t doff = (uint32_t)(r * FPITCH + c * 16);
        const long goff = (qrow0 + r) * D_ + col0 + c * 8;
        CP16(sb + FSM_QHI + doff, Qhi + goff);
        CP16(sb + FSM_QLO + doff, Qlo + goff);
    }
    issueKV(0);
    CP_WAIT0();
    __syncthreads();

    const int m0 = wid * 16;
    uint32_t qh[4][4], ql[4][4];
#pragma unroll
    for (int ks = 0; ks < 4; ks++) {
        const uint32_t ra = (uint32_t)((m0 + (lane & 15)) * FPITCH + ks * 32 + (lane >> 4) * 16);
        ldmx4(qh[ks], sb + FSM_QHI + ra);
        ldmx4(ql[ks], sb + FSM_QLO + ra);
    }

    float o[8][4];
#pragma unroll
    for (int i = 0; i < 8; i++)
#pragma unroll
        for (int j = 0; j < 4; j++) o[i][j] = 0.f;
    float mr0 = -1e30f, mr1 = -1e30f, lr0 = 0.f, lr1 = 0.f;

    const int NT = NKV_ / 64;
    for (int kt = 0; kt < NT; kt++) {
        CP_WAIT0();
        __syncthreads();
        if (kt + 1 < NT) issueKV(kt + 1);

        const uint32_t kb = sb + (uint32_t)((kt & 1) * FST);

        float s[8][4];
#pragma unroll
        for (int i = 0; i < 8; i++)
#pragma unroll
            for (int j = 0; j < 4; j++) s[i][j] = 0.f;

        // ---- S = Q K^T (2-term, Q-side split) ----
#pragma unroll
        for (int ks = 0; ks < 4; ks++) {
#pragma unroll
            for (int ntp = 0; ntp < 4; ntp++) {
                const uint32_t rb = (uint32_t)((ntp * 16 + (lane & 15)) * FPITCH
                                  + ks * 32 + (lane >> 4) * 16);
                uint32_t bh[4];
                ldmx4(bh, kb + rb);
#pragma unroll
                for (int oo = 0; oo < 2; oo++) {
                    float* d = s[ntp * 2 + oo];
                    mma_f16(d, qh[ks], bh[oo], bh[oo + 2]);
                    mma_f16(d, ql[ks], bh[oo], bh[oo + 2]);
                }
            }
        }

        // ---- scale + online softmax ----
#pragma unroll
        for (int i = 0; i < 8; i++)
#pragma unroll
            for (int j = 0; j < 4; j++) s[i][j] *= 0.125f;

        float tm0 = -1e30f, tm1 = -1e30f;
#pragma unroll
        for (int i = 0; i < 8; i++) {
            tm0 = fmaxf(tm0, fmaxf(s[i][0], s[i][1]));
            tm1 = fmaxf(tm1, fmaxf(s[i][2], s[i][3]));
        }
        tm0 = fmaxf(tm0, __shfl_xor_sync(0xffffffffu, tm0, 1));
        tm0 = fmaxf(tm0, __shfl_xor_sync(0xffffffffu, tm0, 2));
        tm1 = fmaxf(tm1, __shfl_xor_sync(0xffffffffu, tm1, 1));
        tm1 = fmaxf(tm1, __shfl_xor_sync(0xffffffffu, tm1, 2));

        const float mn0 = fmaxf(mr0, tm0);
        const float mn1 = fmaxf(mr1, tm1);
        const float cr0 = __expf(mr0 - mn0);
        const float cr1 = __expf(mr1 - mn1);
        mr0 = mn0; mr1 = mn1;

        float ps0 = 0.f, ps1 = 0.f;
#pragma unroll
        for (int i = 0; i < 8; i++) {
            s[i][0] = __expf(s[i][0] - mn0);
            s[i][1] = __expf(s[i][1] - mn0);
            s[i][2] = __expf(s[i][2] - mn1);
            s[i][3] = __expf(s[i][3] - mn1);
            ps0 += s[i][0] + s[i][1];
            ps1 += s[i][2] + s[i][3];
        }
        ps0 += __shfl_xor_sync(0xffffffffu, ps0, 1);
        ps0 += __shfl_xor_sync(0xffffffffu, ps0, 2);
        ps1 += __shfl_xor_sync(0xffffffffu, ps1, 1);
        ps1 += __shfl_xor_sync(0xffffffffu, ps1, 2);
        lr0 = lr0 * cr0 + ps0;
        lr1 = lr1 * cr1 + ps1;

#pragma unroll
        for (int i = 0; i < 8; i++) {
            o[i][0] *= cr0; o[i][1] *= cr0;
            o[i][2] *= cr1; o[i][3] *= cr1;
        }

        // ---- O += (256*P) V  (1-term, P single fp16) ----
#pragma unroll
        for (int ks2 = 0; ks2 < 4; ks2++) {
            const int n0 = 2 * ks2, n1 = 2 * ks2 + 1;
            uint32_t ph[4];
            ph[0] = pack_h2(s[n0][0] * 256.f, s[n0][1] * 256.f);
            ph[1] = pack_h2(s[n0][2] * 256.f, s[n0][3] * 256.f);
            ph[2] = pack_h2(s[n1][0] * 256.f, s[n1][1] * 256.f);
            ph[3] = pack_h2(s[n1][2] * 256.f, s[n1][3] * 256.f);

#pragma unroll
            for (int ntp = 0; ntp < 4; ntp++) {
                const uint32_t rv2 = (uint32_t)((ks2 * 16 + (lane & 15)) * FPITCH
                                   + ntp * 32 + (lane >> 4) * 16);
                uint32_t vh[4];
                ldmx4t(vh, kb + FT + rv2);
#pragma unroll
                for (int o2 = 0; o2 < 2; o2++)
                    mma_f16(o[ntp * 2 + o2], ph, vh[o2 * 2], vh[o2 * 2 + 1]);
            }
        }
    }

    // ---- finalize: normalize (1/(256*l)) + store single fp16 ----
    const float inv0 = 1.f / (256.f * lr0);
    const float inv1 = 1.f / (256.f * lr1);
    const int r = lane >> 2;
    const long orow = (qrow0 + m0 + r) * D_ + col0;
#pragma unroll
    for (int nt = 0; nt < 8; nt++) {
        const int c = nt * 8 + (lane & 3) * 2;
        *(uint32_t*)&O[orow + c]          = pack_h2(o[nt][0] * inv0, o[nt][1] * inv0);
        *(uint32_t*)&O[orow + 8 * D_ + c] = pack_h2(o[nt][2] * inv1, o[nt][3] * inv1);
    }
}

// ===========================================================================
extern "C" void kernel_launch(void* const* d_in, const int* in_sizes, int n_in,
                              void* d_out, int out_size)
{
    const float* q  = (const float*)d_in[0];
    const float* kv = (const float*)d_in[1];
    const float* Wq = (const float*)d_in[2];
    const float* bq = (const float*)d_in[3];
    const float* Wk = (const float*)d_in[4];
    const float* bk = (const float*)d_in[5];
    const float* Wv = (const float*)d_in[6];
    const float* bv = (const float*)d_in[7];
    const float* Wo = (const float*)d_in[8];
    const float* bo = (const float*)d_in[9];
    float* out = (float*)d_out;

    __half *qhi, *qlo, *kvhi, *kvlo, *Wqh, *Wkh, *Wvh, *Woh;
    __half *Qhi, *Qlo, *Kh, *Vh, *Oh;
    cudaGetSymbolAddress((void**)&qhi,  g_qhi);
    cudaGetSymbolAddress((void**)&qlo,  g_qlo);
    cudaGetSymbolAddress((void**)&kvhi, g_kvhi);
    cudaGetSymbolAddress((void**)&kvlo, g_kvlo);
    cudaGetSymbolAddress((void**)&Wqh,  g_Wq);
    cudaGetSymbolAddress((void**)&Wkh,  g_Wk);
    cudaGetSymbolAddress((void**)&Wvh,  g_Wv);
    cudaGetSymbolAddress((void**)&Woh,  g_Wo);
    cudaGetSymbolAddress((void**)&Qhi,  g_Qhi);
    cudaGetSymbolAddress((void**)&Qlo,  g_Qlo);
    cudaGetSymbolAddress((void**)&Kh,   g_K);
    cudaGetSymbolAddress((void**)&Vh,   g_V);
    cudaGetSymbolAddress((void**)&Oh,   g_O);

    const int SMEM2 = 2 * 3 * GT;   // ATERMS=2: 110592
    const int SMEM1 = 2 * 2 * GT;   // ATERMS=1: 73728
    cudaFuncSetAttribute(gemm_ps<2,1>, cudaFuncAttributeMaxDynamicSharedMemorySize, SMEM2);
    cudaFuncSetAttribute(gemm_ps<2,2>, cudaFuncAttributeMaxDynamicSharedMemorySize, SMEM2);
    cudaFuncSetAttribute(gemm_ps<1,0>, cudaFuncAttributeMaxDynamicSharedMemorySize, SMEM1);
    cudaFuncSetAttribute(flash_mma,    cudaFuncAttributeMaxDynamicSharedMemorySize, FSM_TOTAL);

    const int NQK = B_ * NQ_ * D_;     // 4M
    const int NW  = D_ * D_;           // 1M
    split2_kernel<<<NQK / 1024, 256>>>(q,  qhi,  qlo);
    split2_kernel<<<NQK / 1024, 256>>>(kv, kvhi, kvlo);
    round1_kernel<<<NW / 1024, 256>>>(Wq, Wqh);
    round1_kernel<<<NW / 1024, 256>>>(Wk, Wkh);
    round1_kernel<<<NW / 1024, 256>>>(Wv, Wvh);
    round1_kernel<<<NW / 1024, 256>>>(Wo, Woh);

    dim3 ggrid(GN / 128, GM / 128);  // (8, 32)

    gemm_ps<2,1><<<ggrid, 512, SMEM2>>>(qhi,  qlo,  Wqh, bq, nullptr, Qhi, Qlo);
    gemm_ps<2,2><<<ggrid, 512, SMEM2>>>(kvhi, kvlo, Wkh, bk, nullptr, Kh, nullptr);
    gemm_ps<2,2><<<ggrid, 512, SMEM2>>>(kvhi, kvlo, Wvh, bv, nullptr, Vh, nullptr);

    flash_mma<<<dim3(NQ_ / 64, H_, B_), 128, FSM_TOTAL>>>(Qhi, Qlo, Kh, Vh, Oh);

    gemm_ps<1,0><<<ggrid, 512, SMEM1>>>(Oh, nullptr, Woh, bo, out, nullptr, nullptr);
}

// round 17
// speedup vs baseline: 2.9591x; 1.1395x over previous
#include <cuda_runtime.h>
#include <cuda_fp16.h>
#include <math.h>
#include <stdint.h>

#define B_   2
#define NQ_  2048
#define NKV_ 2048
#define D_   1024
#define H_   16
#define DH_  64

// ---- Scratch (allocation-free) ----
__device__ __half g_qhi[B_ * NQ_ * D_],  g_qlo[B_ * NQ_ * D_];
__device__ __half g_kvhi[B_ * NKV_ * D_], g_kvlo[B_ * NKV_ * D_];
__device__ __half g_Wq[D_ * D_], g_Wk[D_ * D_], g_Wv[D_ * D_], g_Wo[D_ * D_];
__device__ __half g_Qhi[B_ * NQ_ * D_], g_Qlo[B_ * NQ_ * D_];
__device__ __half g_K[B_ * NKV_ * D_];
__device__ __half g_V[B_ * NKV_ * D_];
__device__ __half g_O[B_ * NQ_ * D_];

__device__ __forceinline__ uint32_t smem_u32(const void* p) {
    uint32_t a;
    asm("{ .reg .u64 t; cvta.to.shared.u64 t, %1; cvt.u32.u64 %0, t; }"
        : "=r"(a) : "l"(p));
    return a;
}

__device__ __forceinline__ void mma_f16(float* d, const uint32_t* a,
                                        uint32_t b0, uint32_t b1) {
    asm volatile(
        "mma.sync.aligned.m16n8k16.row.col.f32.f16.f16.f32 "
        "{%0,%1,%2,%3}, {%4,%5,%6,%7}, {%8,%9}, {%0,%1,%2,%3};"
        : "+f"(d[0]), "+f"(d[1]), "+f"(d[2]), "+f"(d[3])
        : "r"(a[0]), "r"(a[1]), "r"(a[2]), "r"(a[3]), "r"(b0), "r"(b1));
}

__device__ __forceinline__ void ldmx4(uint32_t* r, uint32_t addr) {
    asm volatile(
        "ldmatrix.sync.aligned.m8n8.x4.shared.b16 {%0,%1,%2,%3}, [%4];"
        : "=r"(r[0]), "=r"(r[1]), "=r"(r[2]), "=r"(r[3]) : "r"(addr));
}

__device__ __forceinline__ void ldmx4t(uint32_t* r, uint32_t addr) {
    asm volatile(
        "ldmatrix.sync.aligned.m8n8.x4.trans.shared.b16 {%0,%1,%2,%3}, [%4];"
        : "=r"(r[0]), "=r"(r[1]), "=r"(r[2]), "=r"(r[3]) : "r"(addr));
}

__device__ __forceinline__ uint32_t pack_h2(float a, float b) {
    __half2 h = __floats2half2_rn(a, b);
    return *(uint32_t*)&h;
}

#define CP16(dst, src) \
    asm volatile("cp.async.cg.shared.global [%0], [%1], 16;" :: "r"(dst), "l"(src))
#define CP_COMMIT() asm volatile("cp.async.commit_group;" ::: "memory")
#define CP_WAIT0()  asm volatile("cp.async.wait_group 0;" ::: "memory")

// ===========================================================================
// split2: fp32 -> fp16 hi/lo.    round4: 4 weight tensors fp32 -> fp16.
// ===========================================================================
__global__ __launch_bounds__(256) void split2_kernel(
    const float* __restrict__ x, __half* __restrict__ hi, __half* __restrict__ lo)
{
    const int i = (blockIdx.x * 256 + threadIdx.x) * 4;
    const float4 v = *(const float4*)(x + i);
    const __half h0 = __float2half_rn(v.x), h1 = __float2half_rn(v.y);
    const __half h2 = __float2half_rn(v.z), h3 = __float2half_rn(v.w);
    uint2 hv, lv;
    hv.x = pack_h2(v.x, v.y);
    hv.y = pack_h2(v.z, v.w);
    lv.x = pack_h2(v.x - __half2float(h0), v.y - __half2float(h1));
    lv.y = pack_h2(v.z - __half2float(h2), v.w - __half2float(h3));
    *(uint2*)(hi + i) = hv;
    *(uint2*)(lo + i) = lv;
}

__global__ __launch_bounds__(256) void round4_kernel(
    const float* __restrict__ x0, const float* __restrict__ x1,
    const float* __restrict__ x2, const float* __restrict__ x3,
    __half* __restrict__ y0, __half* __restrict__ y1,
    __half* __restrict__ y2, __half* __restrict__ y3)
{
    const float* x;
    __half* y;
    switch (blockIdx.y) {
        case 0: x = x0; y = y0; break;
        case 1: x = x1; y = y1; break;
        case 2: x = x2; y = y2; break;
        default: x = x3; y = y3; break;
    }
    const int i = (blockIdx.x * 256 + threadIdx.x) * 4;
    const float4 v = *(const float4*)(x + i);
    uint2 o;
    o.x = pack_h2(v.x, v.y);
    o.y = pack_h2(v.z, v.w);
    *(uint2*)(y + i) = o;
}

// ===========================================================================
// fp16 HMMA GEMM: C = A[M,K] @ W[N,K]^T + bias.
// ATERMS=2: A split (hi,lo). ATERMS=1: A single fp16.
// CTA 128x128, K-chunk 64, 512 threads (4x4 warps), double-buffered cp.async.
// OUTMODE 0: fp32. 1: split fp16. 2: single fp16.
// ===========================================================================
#define GM 4096
#define GN 1024
#define GK 1024
#define GPITCH 144
#define GT  (128 * GPITCH)             // 18432 per tile

template <int ATERMS, int OUTMODE>
__global__ __launch_bounds__(512) void gemm_ps(
    const __half* __restrict__ Ahi, const __half* __restrict__ Alo,
    const __half* __restrict__ W,
    const float* __restrict__ bias, float* __restrict__ C,
    __half* __restrict__ Chi, __half* __restrict__ Clo)
{
    constexpr int NTILES = ATERMS + 1;
    constexpr int GST = NTILES * GT;
    extern __shared__ char smem[];
    const uint32_t sb = smem_u32(smem);
    const int tid  = threadIdx.x;
    const int wid  = tid >> 5;
    const int lane = tid & 31;
    const int bm = blockIdx.y * 128;
    const int bn = blockIdx.x * 128;
    const int warp_m = wid >> 2;
    const int warp_n = wid & 3;

    float acc[2][4][4];
#pragma unroll
    for (int i = 0; i < 2; i++)
#pragma unroll
        for (int j = 0; j < 4; j++)
#pragma unroll
            for (int k = 0; k < 4; k++) acc[i][j][k] = 0.f;

    auto issue_chunk = [&](int chunk) {
        const uint32_t base = sb + (uint32_t)((chunk & 1) * GST);
        const int kc = chunk * 64;
#pragma unroll
        for (int it = 0; it < 2 * NTILES; it++) {
            const int t   = it >> 1;
            const int sub = (it & 1) * 512 + tid;
            const int r   = sub >> 3;
            const int c   = sub & 7;
            const uint32_t dst = base + (uint32_t)(t * GT + r * GPITCH + c * 16);
            const __half* src;
            if (t == 0)                     src = Ahi + (long)(bm + r) * GK + kc + c * 8;
            else if (ATERMS == 2 && t == 1) src = Alo + (long)(bm + r) * GK + kc + c * 8;
            else                            src = W   + (long)(bn + r) * GK + kc + c * 8;
            CP16(dst, src);
        }
        CP_COMMIT();
    };

    issue_chunk(0);

    for (int chunk = 0; chunk < GK / 64; chunk++) {
        CP_WAIT0();
        __syncthreads();
        if (chunk + 1 < GK / 64) issue_chunk(chunk + 1);

        const uint32_t base = sb + (uint32_t)((chunk & 1) * GST);
#pragma unroll
        for (int ks = 0; ks < 4; ks++) {
            uint32_t ah[2][4], al[2][4];
#pragma unroll
            for (int mt = 0; mt < 2; mt++) {
                const uint32_t ra = (uint32_t)((warp_m * 32 + mt * 16 + (lane & 15)) * GPITCH
                                  + ks * 32 + (lane >> 4) * 16);
                ldmx4(ah[mt], base + ra);
                if (ATERMS == 2) ldmx4(al[mt], base + GT + ra);
            }
            uint32_t bh[2][4];
#pragma unroll
            for (int nt2 = 0; nt2 < 2; nt2++) {
                const uint32_t rb = (uint32_t)((warp_n * 32 + nt2 * 16 + (lane & 15)) * GPITCH
                                  + ks * 32 + (lane >> 4) * 16);
                ldmx4(bh[nt2], base + (NTILES - 1) * GT + rb);
            }
#pragma unroll
            for (int mt = 0; mt < 2; mt++) {
#pragma unroll
                for (int nt = 0; nt < 4; nt++) {
                    const int g = nt >> 1, o = nt & 1;
                    mma_f16(acc[mt][nt], ah[mt], bh[g][o], bh[g][o + 2]);
                    if (ATERMS == 2)
                        mma_f16(acc[mt][nt], al[mt], bh[g][o], bh[g][o + 2]);
                }
            }
        }
    }

    const int rq = lane >> 2;
    const int cq = (lane & 3) * 2;
#pragma unroll
    for (int mt = 0; mt < 2; mt++) {
        const int r0 = bm + warp_m * 32 + mt * 16 + rq;
#pragma unroll
        for (int nt = 0; nt < 4; nt++) {
            const int c = bn + warp_n * 32 + nt * 8 + cq;
            const float2 bv = *(const float2*)&bias[c];
            const float v0 = acc[mt][nt][0] + bv.x;
            const float v1 = acc[mt][nt][1] + bv.y;
            const float v2 = acc[mt][nt][2] + bv.x;
            const float v3 = acc[mt][nt][3] + bv.y;
            if (OUTMODE == 0) {
                *(float2*)&C[(long)r0 * GN + c]       = make_float2(v0, v1);
                *(float2*)&C[(long)(r0 + 8) * GN + c] = make_float2(v2, v3);
            } else if (OUTMODE == 2) {
                *(uint32_t*)&Chi[(long)r0 * GN + c]       = pack_h2(v0, v1);
                *(uint32_t*)&Chi[(long)(r0 + 8) * GN + c] = pack_h2(v2, v3);
            } else {
                const float h0 = __half2float(__float2half_rn(v0));
                const float h1 = __half2float(__float2half_rn(v1));
                const float h2 = __half2float(__float2half_rn(v2));
                const float h3 = __half2float(__float2half_rn(v3));
                *(uint32_t*)&Chi[(long)r0 * GN + c]       = pack_h2(v0, v1);
                *(uint32_t*)&Chi[(long)(r0 + 8) * GN + c] = pack_h2(v2, v3);
                *(uint32_t*)&Clo[(long)r0 * GN + c]       = pack_h2(v0 - h0, v1 - h1);
                *(uint32_t*)&Clo[(long)(r0 + 8) * GN + c] = pack_h2(v2 - h2, v3 - h3);
            }
        }
    }
}

// ===========================================================================
// fp16 HMMA flash attention (unchanged from R16, validated).
// Q split (2-term QK), K/V single fp16, P single fp16 x256 (1-term PV).
// ===========================================================================
#define FPITCH 144
#define FT  (64 * FPITCH)
#define FST (2 * FT)
#define FSM_QHI (FST)
#define FSM_QLO (FST + FT)
#define FSM_TOTAL (2 * FST)        // 36864

__global__ __launch_bounds__(128) void flash_mma(
    const __half* __restrict__ Qhi, const __half* __restrict__ Qlo,
    const __half* __restrict__ Ks,  const __half* __restrict__ Vs,
    __half* __restrict__ O)
{
    extern __shared__ char smem[];
    const uint32_t sb = smem_u32(smem);
    const int tid  = threadIdx.x;
    const int wid  = tid >> 5;
    const int lane = tid & 31;
    const int qt = blockIdx.x, h = blockIdx.y, b = blockIdx.z;

    const long qrow0 = (long)b * NQ_ + qt * 64;
    const long krow0 = (long)b * NKV_;
    const int  col0  = h * DH_;

    auto issueKV = [&](int kt) {
        const uint32_t base = sb + (uint32_t)((kt & 1) * FST);
#pragma unroll
        for (int it = 0; it < 4; it++) {
            const int idx = it * 128 + tid;
            const int r = idx >> 3, c = idx & 7;
            const uint32_t doff = (uint32_t)(r * FPITCH + c * 16);
            const long goff = (krow0 + kt * 64 + r) * D_ + col0 + c * 8;
            CP16(base + doff,      Ks + goff);
            CP16(base + FT + doff, Vs + goff);
        }
        CP_COMMIT();
    };

#pragma unroll
    for (int it = 0; it < 4; it++) {
        const int idx = it * 128 + tid;
        const int r = idx >> 3, c = idx & 7;
        const uint32_t doff = (uint32_t)(r * FPITCH + c * 16);
        const long goff = (qrow0 + r) * D_ + col0 + c * 8;
        CP16(sb + FSM_QHI + doff, Qhi + goff);
        CP16(sb + FSM_QLO + doff, Qlo + goff);
    }
    issueKV(0);
    CP_WAIT0();
    __syncthreads();

    const int m0 = wid * 16;
    uint32_t qh[4][4], ql[4][4];
#pragma unroll
    for (int ks = 0; ks < 4; ks++) {
        const uint32_t ra = (uint32_t)((m0 + (lane & 15)) * FPITCH + ks * 32 + (lane >> 4) * 16);
        ldmx4(qh[ks], sb + FSM_QHI + ra);
        ldmx4(ql[ks], sb + FSM_QLO + ra);
    }

    float o[8][4];
#pragma unroll
    for (int i = 0; i < 8; i++)
#pragma unroll
        for (int j = 0; j < 4; j++) o[i][j] = 0.f;
    float mr0 = -1e30f, mr1 = -1e30f, lr0 = 0.f, lr1 = 0.f;

    const int NT = NKV_ / 64;
    for (int kt = 0; kt < NT; kt++) {
        CP_WAIT0();
        __syncthreads();
        if (kt + 1 < NT) issueKV(kt + 1);

        const uint32_t kb = sb + (uint32_t)((kt & 1) * FST);

        float s[8][4];
#pragma unroll
        for (int i = 0; i < 8; i++)
#pragma unroll
            for (int j = 0; j < 4; j++) s[i][j] = 0.f;

#pragma unroll
        for (int ks = 0; ks < 4; ks++) {
#pragma unroll
            for (int ntp = 0; ntp < 4; ntp++) {
                const uint32_t rb = (uint32_t)((ntp * 16 + (lane & 15)) * FPITCH
                                  + ks * 32 + (lane >> 4) * 16);
                uint32_t bh[4];
                ldmx4(bh, kb + rb);
#pragma unroll
                for (int oo = 0; oo < 2; oo++) {
                    float* d = s[ntp * 2 + oo];
                    mma_f16(d, qh[ks], bh[oo], bh[oo + 2]);
                    mma_f16(d, ql[ks], bh[oo], bh[oo + 2]);
                }
            }
        }

#pragma unroll
        for (int i = 0; i < 8; i++)
#pragma unroll
            for (int j = 0; j < 4; j++) s[i][j] *= 0.125f;

        float tm0 = -1e30f, tm1 = -1e30f;
#pragma unroll
        for (int i = 0; i < 8; i++) {
            tm0 = fmaxf(tm0, fmaxf(s[i][0], s[i][1]));
            tm1 = fmaxf(tm1, fmaxf(s[i][2], s[i][3]));
        }
        tm0 = fmaxf(tm0, __shfl_xor_sync(0xffffffffu, tm0, 1));
        tm0 = fmaxf(tm0, __shfl_xor_sync(0xffffffffu, tm0, 2));
        tm1 = fmaxf(tm1, __shfl_xor_sync(0xffffffffu, tm1, 1));
        tm1 = fmaxf(tm1, __shfl_xor_sync(0xffffffffu, tm1, 2));

        const float mn0 = fmaxf(mr0, tm0);
        const float mn1 = fmaxf(mr1, tm1);
        const float cr0 = __expf(mr0 - mn0);
        const float cr1 = __expf(mr1 - mn1);
        mr0 = mn0; mr1 = mn1;

        float ps0 = 0.f, ps1 = 0.f;
#pragma unroll
        for (int i = 0; i < 8; i++) {
            s[i][0] = __expf(s[i][0] - mn0);
            s[i][1] = __expf(s[i][1] - mn0);
            s[i][2] = __expf(s[i][2] - mn1);
            s[i][3] = __expf(s[i][3] - mn1);
            ps0 += s[i][0] + s[i][1];
            ps1 += s[i][2] + s[i][3];
        }
        ps0 += __shfl_xor_sync(0xffffffffu, ps0, 1);
        ps0 += __shfl_xor_sync(0xffffffffu, ps0, 2);
        ps1 += __shfl_xor_sync(0xffffffffu, ps1, 1);
        ps1 += __shfl_xor_sync(0xffffffffu, ps1, 2);
        lr0 = lr0 * cr0 + ps0;
        lr1 = lr1 * cr1 + ps1;

#pragma unroll
        for (int i = 0; i < 8; i++) {
            o[i][0] *= cr0; o[i][1] *= cr0;
            o[i][2] *= cr1; o[i][3] *= cr1;
        }

#pragma unroll
        for (int ks2 = 0; ks2 < 4; ks2++) {
            const int n0 = 2 * ks2, n1 = 2 * ks2 + 1;
            uint32_t ph[4];
            ph[0] = pack_h2(s[n0][0] * 256.f, s[n0][1] * 256.f);
            ph[1] = pack_h2(s[n0][2] * 256.f, s[n0][3] * 256.f);
            ph[2] = pack_h2(s[n1][0] * 256.f, s[n1][1] * 256.f);
            ph[3] = pack_h2(s[n1][2] * 256.f, s[n1][3] * 256.f);

#pragma unroll
            for (int ntp = 0; ntp < 4; ntp++) {
                const uint32_t rv2 = (uint32_t)((ks2 * 16 + (lane & 15)) * FPITCH
                                   + ntp * 32 + (lane >> 4) * 16);
                uint32_t vh[4];
                ldmx4t(vh, kb + FT + rv2);
#pragma unroll
                for (int o2 = 0; o2 < 2; o2++)
                    mma_f16(o[ntp * 2 + o2], ph, vh[o2 * 2], vh[o2 * 2 + 1]);
            }
        }
    }

    const float inv0 = 1.f / (256.f * lr0);
    const float inv1 = 1.f / (256.f * lr1);
    const int r = lane >> 2;
    const long orow = (qrow0 + m0 + r) * D_ + col0;
#pragma unroll
    for (int nt = 0; nt < 8; nt++) {
        const int c = nt * 8 + (lane & 3) * 2;
        *(uint32_t*)&O[orow + c]          = pack_h2(o[nt][0] * inv0, o[nt][1] * inv0);
        *(uint32_t*)&O[orow + 8 * D_ + c] = pack_h2(o[nt][2] * inv1, o[nt][3] * inv1);
    }
}

// ===========================================================================
extern "C" void kernel_launch(void* const* d_in, const int* in_sizes, int n_in,
                              void* d_out, int out_size)
{
    const float* q  = (const float*)d_in[0];
    const float* kv = (const float*)d_in[1];
    const float* Wq = (const float*)d_in[2];
    const float* bq = (const float*)d_in[3];
    const float* Wk = (const float*)d_in[4];
    const float* bk = (const float*)d_in[5];
    const float* Wv = (const float*)d_in[6];
    const float* bv = (const float*)d_in[7];
    const float* Wo = (const float*)d_in[8];
    const float* bo = (const float*)d_in[9];
    float* out = (float*)d_out;

    __half *qhi, *qlo, *kvhi, *kvlo, *Wqh, *Wkh, *Wvh, *Woh;
    __half *Qhi, *Qlo, *Kh, *Vh, *Oh;
    cudaGetSymbolAddress((void**)&qhi,  g_qhi);
    cudaGetSymbolAddress((void**)&qlo,  g_qlo);
    cudaGetSymbolAddress((void**)&kvhi, g_kvhi);
    cudaGetSymbolAddress((void**)&kvlo, g_kvlo);
    cudaGetSymbolAddress((void**)&Wqh,  g_Wq);
    cudaGetSymbolAddress((void**)&Wkh,  g_Wk);
    cudaGetSymbolAddress((void**)&Wvh,  g_Wv);
    cudaGetSymbolAddress((void**)&Woh,  g_Wo);
    cudaGetSymbolAddress((void**)&Qhi,  g_Qhi);
    cudaGetSymbolAddress((void**)&Qlo,  g_Qlo);
    cudaGetSymbolAddress((void**)&Kh,   g_K);
    cudaGetSymbolAddress((void**)&Vh,   g_V);
    cudaGetSymbolAddress((void**)&Oh,   g_O);

    const int SMEM2 = 2 * 3 * GT;   // ATERMS=2: 110592
    const int SMEM1 = 2 * 2 * GT;   // ATERMS=1: 73728
    cudaFuncSetAttribute(gemm_ps<2,1>, cudaFuncAttributeMaxDynamicSharedMemorySize, SMEM2);
    cudaFuncSetAttribute(gemm_ps<1,2>, cudaFuncAttributeMaxDynamicSharedMemorySize, SMEM1);
    cudaFuncSetAttribute(gemm_ps<1,0>, cudaFuncAttributeMaxDynamicSharedMemorySize, SMEM1);
    cudaFuncSetAttribute(flash_mma,    cudaFuncAttributeMaxDynamicSharedMemorySize, FSM_TOTAL);

    const int NQK = B_ * NQ_ * D_;     // 4M
    const int NW  = D_ * D_;           // 1M
    split2_kernel<<<NQK / 1024, 256>>>(q,  qhi,  qlo);
    split2_kernel<<<NQK / 1024, 256>>>(kv, kvhi, kvlo);
    round4_kernel<<<dim3(NW / 1024, 4), 256>>>(Wq, Wk, Wv, Wo, Wqh, Wkh, Wvh, Woh);

    dim3 ggrid(GN / 128, GM / 128);  // (8, 32)

    // Q-projection: split A (protects exp-amplified score path)
    gemm_ps<2,1><<<ggrid, 512, SMEM2>>>(qhi,  qlo,  Wqh, bq, nullptr, Qhi, Qlo);
    // K/V projections: single-rounded kv A-side (error averaged by softmax)
    gemm_ps<1,2><<<ggrid, 512, SMEM1>>>(kvhi, nullptr, Wkh, bk, nullptr, Kh, nullptr);
    gemm_ps<1,2><<<ggrid, 512, SMEM1>>>(kvhi, nullptr, Wvh, bv, nullptr, Vh, nullptr);

    flash_mma<<<dim3(NQ_ / 64, H_, B_), 128, FSM_TOTAL>>>(Qhi, Qlo, Kh, Vh, Oh);

    gemm_ps<1,0><<<ggrid, 512, SMEM1>>>(Oh, nullptr, Woh, bo, out, nullptr, nullptr);
}